// round 1
// baseline (speedup 1.0000x reference)
#include <cuda_runtime.h>

// AnisotropicDistance:
//   along[b,i,j]   = pd_self[i] - p_j . t_i
//   sq_dist[b,i,j] = sq_i + sq_j - 2 * (p_i . p_j)
//   normal_sq      = max(sq_dist + along^2 * (||t_i||^2 - 2), 0)
//   out            = alpha_i * normal_sq + beta_i * along^2
// Folded (alpha > 0):
//   out = max(alpha*sq_i + alpha*sq_j - 2alpha*(pi.pj) + alpha*(tn2-2)*along^2, 0)
//         + beta*along^2
//
// Tiling: block = 256 threads = 64 j-threads (4 j each, float4 store) x 4 i-groups
//         (8 i each).  Block tile: 256 j x 32 i.  Warp = 32 j-threads sharing one
//         i-group -> per-i constants are LDS broadcasts.

#define TJ 256
#define TI 32
#define IPER 8
#define NTHREADS 256

__device__ __forceinline__ float aniso_elem(
    float px, float py, float pz, float sj,
    const float4 A,   // (-tx, -ty, -tz, pd_self)
    const float4 Bc,  // (pix, piy, piz, alpha*sq_i)
    const float4 C)   // (alpha, -2*alpha, alpha*(tn2-2), beta)
{
    float along = fmaf(A.x, px, fmaf(A.y, py, fmaf(A.z, pz, A.w)));
    float dp    = fmaf(Bc.x, px, fmaf(Bc.y, py, Bc.z * pz));
    float al2   = along * along;
    float v     = fmaf(C.x, sj, Bc.w);   // alpha*sq_j + alpha*sq_i
    v           = fmaf(C.y, dp, v);      // - 2*alpha*(pi.pj)
    v           = fmaf(C.z, al2, v);     // + alpha*(tn2-2)*along^2
    v           = fmaxf(v, 0.0f);
    return fmaf(C.w, al2, v);            // + beta*along^2
}

__global__ __launch_bounds__(NTHREADS)
void AnisotropicDistance_kernel(
    const float* __restrict__ points,
    const float* __restrict__ pdir,
    const float* __restrict__ lin,
    float* __restrict__ out,
    int N)
{
    __shared__ float4 si[TI][3];

    const int b  = blockIdx.z;
    const int i0 = blockIdx.y * TI;
    const int j0 = blockIdx.x * TJ;
    const int t  = threadIdx.x;

    // ---- preamble: threads 0..31 build per-i packed constants ----
    if (t < TI) {
        const int i = i0 + t;
        const size_t base = ((size_t)b * N + i) * 3;
        const float px = points[base + 0];
        const float py = points[base + 1];
        const float pz = points[base + 2];
        const float tx = pdir[base + 0];
        const float ty = pdir[base + 1];
        const float tz = pdir[base + 2];
        const float l  = lin[(size_t)b * N + i];

        const float alpha   = 2.0f * (1.0f + l);
        const float beta    = 0.5f * (1.0f - l);
        const float pd_self = fmaf(px, tx, fmaf(py, ty, pz * tz));
        const float sq_i    = fmaf(px, px, fmaf(py, py, pz * pz));
        const float tn2     = fmaf(tx, tx, fmaf(ty, ty, tz * tz));

        si[t][0] = make_float4(-tx, -ty, -tz, pd_self);
        si[t][1] = make_float4(px, py, pz, alpha * sq_i);
        si[t][2] = make_float4(alpha, -2.0f * alpha, alpha * (tn2 - 2.0f), beta);
    }
    __syncthreads();

    // ---- per-thread j quad: 4 consecutive points = 3 aligned float4 loads ----
    const int jt = t & 63;          // 0..63
    const int ig = t >> 6;          // i-group 0..3
    const int j  = j0 + jt * 4;

    const float4* pj4 = reinterpret_cast<const float4*>(points + ((size_t)b * N + j) * 3);
    const float4 q0 = pj4[0];
    const float4 q1 = pj4[1];
    const float4 q2 = pj4[2];

    const float p0x = q0.x, p0y = q0.y, p0z = q0.z;
    const float p1x = q0.w, p1y = q1.x, p1z = q1.y;
    const float p2x = q1.z, p2y = q1.w, p2z = q2.x;
    const float p3x = q2.y, p3y = q2.z, p3z = q2.w;

    const float s0 = fmaf(p0x, p0x, fmaf(p0y, p0y, p0z * p0z));
    const float s1 = fmaf(p1x, p1x, fmaf(p1y, p1y, p1z * p1z));
    const float s2 = fmaf(p2x, p2x, fmaf(p2y, p2y, p2z * p2z));
    const float s3 = fmaf(p3x, p3x, fmaf(p3y, p3y, p3z * p3z));

    float* orow = out + ((size_t)b * N + (size_t)(i0 + ig * IPER)) * (size_t)N + j;
    const size_t rowstride = (size_t)N;

#pragma unroll
    for (int ii = 0; ii < IPER; ii++) {
        const int il = ig * IPER + ii;
        const float4 A  = si[il][0];
        const float4 Bc = si[il][1];
        const float4 C  = si[il][2];

        float4 r;
        r.x = aniso_elem(p0x, p0y, p0z, s0, A, Bc, C);
        r.y = aniso_elem(p1x, p1y, p1z, s1, A, Bc, C);
        r.z = aniso_elem(p2x, p2y, p2z, s2, A, Bc, C);
        r.w = aniso_elem(p3x, p3y, p3z, s3, A, Bc, C);

        *reinterpret_cast<float4*>(orow) = r;
        orow += rowstride;
    }
}

extern "C" void kernel_launch(void* const* d_in, const int* in_sizes, int n_in,
                              void* d_out, int out_size)
{
    const float* points = (const float*)d_in[0];
    const float* pdir   = (const float*)d_in[1];
    const float* lin    = (const float*)d_in[2];
    float* out          = (float*)d_out;

    // in_sizes[2] = B*N (linearity), out_size = B*N*N  ->  N = out_size / (B*N)
    const long long BN = in_sizes[2];
    const int N = (int)((long long)out_size / BN);
    const int B = (int)(BN / N);

    dim3 grid(N / TJ, N / TI, B);
    AnisotropicDistance_kernel<<<grid, NTHREADS>>>(points, pdir, lin, out, N);
}